// round 17
// baseline (speedup 1.0000x reference)
#include <cuda_runtime.h>
#include <math.h>
#include <float.h>

#define BB 16
#define SS 64
#define MM 2048
#define DD 256
#define TK 8
#define OV 512
#define NB 128
#define NT 1024
#define SCALE 0.0625f

typedef unsigned long long ull;

// ---- persistent state (no runtime allocs) ----
__device__ float g_ovl[BB*OV*DD];
__device__ int   g_slot[BB*MM];
__device__ int   g_ovcnt[BB];
__device__ __align__(16) float g_qk[SS*BB*DD];
__device__ __align__(16) float g_gx[SS*BB*DD];
__device__ float g_AT[DD*DD];
__device__ float g_avec[DD];
__device__ float g_WuT1[DD*DD];
__device__ float g_W2[DD*DD];
__device__ float g_cvec[DD];
__device__ __align__(16) float g_psum[BB*NB];      // [b][k]
__device__ __align__(16) float g_part[NB*DD*BB];   // [k][d][b]
__device__ __align__(16) float g_h[DD*BB];         // [j][b]
__device__ __align__(16) ull   g_ck[NB*BB*TK];     // packed candidates
__device__ int   g_tk[BB*TK*3];
// monotonic barrier state (zero at module load, advances every launch)
__device__ int   g_flag[NB*32];
__device__ int   g_gen2;

// =================== flag-array grid barrier (coordinator = block NB-1) ===================
__device__ __forceinline__ void gbar(int target){
  __syncthreads();
  int tid = threadIdx.x, blk = blockIdx.x;
  if (blk == NB-1){
    if (tid < NB-1){
      int v;
      do {
        asm volatile("ld.acquire.gpu.global.s32 %0, [%1];"
                     : "=r"(v) : "l"(&g_flag[tid*32]) : "memory");
      } while (v < target);
    }
    __syncthreads();
    if (tid == 0)
      asm volatile("st.release.gpu.global.s32 [%0], %1;"
                   :: "l"(&g_gen2), "r"(target) : "memory");
  } else {
    if (tid == 0){
      asm volatile("st.release.gpu.global.s32 [%0], %1;"
                   :: "l"(&g_flag[blk*32]), "r"(target) : "memory");
      int v;
      do {
        asm volatile("ld.acquire.gpu.global.s32 %0, [%1];"
                     : "=r"(v) : "l"(&g_gen2) : "memory");
      } while (v < target);
    }
    __syncthreads();
  }
}

// ---- packed f32x2 helpers ----
__device__ __forceinline__ void fma2(ull &d, ull a, ull b){
  asm("fma.rn.f32x2 %0, %1, %2, %0;" : "+l"(d) : "l"(a), "l"(b));
}
__device__ __forceinline__ ull pk2(float lo, float hi){
  ull r; asm("mov.b64 %0, {%1, %2};" : "=l"(r) : "f"(lo), "f"(hi)); return r;
}
__device__ __forceinline__ float upk_sum(ull v){
  float lo, hi; asm("mov.b64 {%0, %1}, %2;" : "=f"(lo), "=f"(hi) : "l"(v));
  return lo + hi;
}
__device__ __forceinline__ float upk_sel(ull v, int hi_sel){
  float lo, hi; asm("mov.b64 {%0, %1}, %2;" : "=f"(lo), "=f"(hi) : "l"(v));
  return hi_sel ? hi : lo;
}

// =================== the single kernel (1024 threads) ===================
__global__ void __launch_bounds__(NT, 1)
persist(const float* __restrict__ x, const float* __restrict__ base,
        const float* __restrict__ Wq, const float* __restrict__ bq,
        const float* __restrict__ Wk, const float* __restrict__ Wv,
        const float* __restrict__ bv, const float* __restrict__ Wu,
        const float* __restrict__ bu, float* __restrict__ out){
  extern __shared__ float dsm[];
  float* rowsf = dsm;          // [16][256]
  float* qks   = dsm + 4096;   // [16][256]
  float* sbuf  = dsm + 8192;   // AB: spart[d][b] ; C2: h[j][b]

  __shared__ float sc[16][17];
  __shared__ __align__(16) ull esm2[128];       // [rp][b] packed (e[2rp],e[2rp+1])
  __shared__ int   dlist[256];
  __shared__ int   dcnt_s;
  __shared__ __align__(16) ull wtop[128];
  __shared__ __align__(16) float4 hred4[256];
  __shared__ __align__(16) float wrow[4*DD];
  __shared__ float cacc[16][4][33];
  __shared__ float sgate[16][2];
  __shared__ int   tk_s[BB*TK*3];
  __shared__ float zin_s[16];
  __shared__ float sbv[2], scv[2];

  int blk = blockIdx.x, tid = threadIdx.x;
  int m0 = blk*16;
  int wid = tid>>5, lane = tid&31;
  int dd0 = blk*2;

  int T0;
  asm volatile("ld.acquire.gpu.global.s32 %0, [%1];" : "=r"(T0) : "l"(&g_gen2) : "memory");

  // ================= init stage 1 =================
  if (blk < 32){                       // WuT1[j][d] = Wu[d][j]
    int base0 = blk*2048;
    #pragma unroll
    for (int z=0;z<2;z++){ int e = base0 + z*1024 + tid; int d = e>>8, j = e&255;
      g_WuT1[j*DD+d] = Wu[(size_t)d*2*DD + j]; }
  } else if (blk < 48){                // A tiles: g_AT[j][d]
    float (*aq)[68] = (float(*)[68])dsm;
    float (*ak)[68] = (float(*)[68])(dsm + 16*68);
    int tn = blk-32, j0 = (tn>>2)*64, d0 = (tn&3)*64;
    int ty = (tid&255)>>4, tx = tid&15;
    float acc[16];
    #pragma unroll
    for (int z=0;z<16;z++) acc[z]=0.f;
    for (int ib=0; ib<DD; ib+=16){
      { int i = tid>>6, j = tid&63;
        aq[i][j] = Wq[(size_t)(ib+i)*DD + j0 + j];
        ak[i][j] = Wk[(size_t)(ib+i)*DD + d0 + j]; }
      __syncthreads();
      if (tid < 256){
        #pragma unroll
        for (int i=0;i<16;i++){
          float qv[4], kv[4];
          #pragma unroll
          for (int u=0;u<4;u++){ qv[u]=aq[i][ty*4+u]; kv[u]=ak[i][tx*4+u]; }
          #pragma unroll
          for (int jr=0;jr<4;jr++)
            #pragma unroll
            for (int dr=0;dr<4;dr++) acc[jr*4+dr] = fmaf(qv[jr], kv[dr], acc[jr*4+dr]);
        }
      }
      __syncthreads();
    }
    if (tid < 256){
      #pragma unroll
      for (int jr=0;jr<4;jr++)
        #pragma unroll
        for (int dr=0;dr<4;dr++)
          g_AT[(size_t)(j0+ty*4+jr)*DD + d0+tx*4+dr] = acc[jr*4+dr]*SCALE;
    }
  } else if (blk < 64){                // W2 tiles [d][i]
    float (*wv)[68] = (float(*)[68])dsm;
    float (*wu)[68] = (float(*)[68])(dsm + 16*68);
    int tn = blk-48, i0 = (tn>>2)*64, d0 = (tn&3)*64;
    int ty = (tid&255)>>4, tx = tid&15;
    float acc[16];
    #pragma unroll
    for (int z=0;z<16;z++) acc[z]=0.f;
    for (int jb=0; jb<DD; jb+=16){
      { int jj = tid>>6, ii = tid&63;
        wv[jj][ii] = Wv[(size_t)(jb+jj)*DD + i0 + ii];
        wu[jj][ii] = Wu[(size_t)(d0+ii)*2*DD + DD + jb + jj]; }
      __syncthreads();
      if (tid < 256){
        #pragma unroll
        for (int jj=0;jj<16;jj++){
          float vv[4], uv[4];
          #pragma unroll
          for (int u=0;u<4;u++){ vv[u]=wv[jj][ty*4+u]; uv[u]=wu[jj][tx*4+u]; }
          #pragma unroll
          for (int ir=0;ir<4;ir++)
            #pragma unroll
            for (int dr=0;dr<4;dr++) acc[ir*4+dr] = fmaf(vv[ir], uv[dr], acc[ir*4+dr]);
        }
      }
      __syncthreads();
    }
    if (tid < 256){
      #pragma unroll
      for (int ir=0;ir<4;ir++)
        #pragma unroll
        for (int dr=0;dr<4;dr++)
          g_W2[(size_t)(d0+tx*4+dr)*DD + i0+ty*4+ir] = acc[ir*4+dr];
    }
  } else if (blk < 80){                // slot map clear
    int base0 = (blk-64)*2048;
    #pragma unroll
    for (int z=0;z<2;z++) g_slot[base0 + z*1024 + tid] = -1;
  } else if (blk == 80){
    if (tid < BB) g_ovcnt[tid] = 0;
  } else if (blk == 81){               // avec
    __shared__ float bqs[DD];
    if (tid < 256) bqs[tid] = bq[tid];
    __syncthreads();
    if (tid < 256){
      float acc = 0.f;
      #pragma unroll 4
      for (int i=0;i<DD;i++) acc = fmaf(Wk[(size_t)i*DD+tid], bqs[i], acc);
      g_avec[tid] = acc*SCALE;
    }
  } else if (blk == 82){               // cvec
    __shared__ float bvs[DD];
    if (tid < 256) bvs[tid] = bv[tid];
    __syncthreads();
    if (tid < 256){
      float acc = 0.f;
      #pragma unroll 4
      for (int j=0;j<DD;j++) acc = fmaf(Wu[(size_t)tid*2*DD + DD + j], bvs[j], acc);
      g_cvec[tid] = acc;
    }
  }
  gbar(T0+1);

  // ================= init stage 2: qk / gx GEMMs =================
  {
    float (*xt)[17] = (float(*)[17])dsm;
    float (*wt)[68] = (float(*)[68])(dsm + 64*17);
    int which = blk>>6;
    int r = blk&63;
    int s0 = (r>>2)*64, d0 = (r&3)*64;
    const float* W = which ? g_WuT1 : g_AT;
    int ty = (tid&255)>>4, tx = tid&15;
    float acc[16];
    #pragma unroll
    for (int z=0;z<16;z++) acc[z]=0.f;
    for (int jb=0; jb<DD; jb+=16){
      if (tid < 256){
        int ss = tid>>2, jq = tid&3;
        float4 xv = *(const float4*)&x[(size_t)(s0+ss)*DD + jb + jq*4];
        xt[ss][jq*4+0]=xv.x; xt[ss][jq*4+1]=xv.y; xt[ss][jq*4+2]=xv.z; xt[ss][jq*4+3]=xv.w;
      }
      { int jj = tid>>6, dd = tid&63;
        wt[jj][dd] = W[(size_t)(jb+jj)*DD + d0 + dd]; }
      __syncthreads();
      if (tid < 256){
        #pragma unroll
        for (int jj=0;jj<16;jj++){
          float xv[4], wv4[4];
          #pragma unroll
          for (int u=0;u<4;u++){ xv[u]=xt[ty*4+u][jj]; wv4[u]=wt[jj][tx*4+u]; }
          #pragma unroll
          for (int sr=0;sr<4;sr++)
            #pragma unroll
            for (int dr=0;dr<4;dr++) acc[sr*4+dr] = fmaf(xv[sr], wv4[dr], acc[sr*4+dr]);
        }
      }
      __syncthreads();
    }
    if (tid < 256){
      float* dst = which ? g_gx : g_qk;
      const float* bias = which ? bu : g_avec;
      #pragma unroll
      for (int sr=0;sr<4;sr++){
        int s = s0 + ty*4 + sr;
        int b = s>>6, t = s&63;
        size_t ro = (size_t)(t*BB+b)*DD + d0 + tx*4;
        #pragma unroll
        for (int dr=0;dr<4;dr++) dst[ro+dr] = acc[sr*4+dr] + bias[d0+tx*4+dr];
      }
    }
  }
  gbar(T0+2);

  // ================= persistent smem loads =================
  for (int i=tid;i<16*DD;i+=NT) rowsf[i] = base[(size_t)m0*DD + i];
  {
    const float4* q4 = (const float4*)g_qk;
    float4* qd = (float4*)qks;
    for (int i=tid;i<1024;i+=NT) qd[i] = __ldcg(&q4[i]);
  }
  { int i = tid; if (i < 2*DD){ wrow[i] = Wv[(size_t)dd0*DD + i]; wrow[2*DD+i] = g_W2[(size_t)dd0*DD + i]; } }
  if (tid<2){ sbv[tid] = bv[dd0+tid]; scv[tid] = g_cvec[dd0+tid]; }
  __syncthreads();

  int sg_bq0 = (wid&7)*2, sg_r0 = (wid>>3)*4, sg_j0 = lane*8;

  int bid = T0+2;
  for (int t=0;t<SS;t++){
    // ================= Phase AB =================
    if (tid==0) dcnt_s = 0;
    __syncthreads();
    if (tid < 256){
      int b = tid>>4, r = tid&15;
      int s = __ldcg(&g_slot[b*MM + m0 + r]);
      if (s >= 0){ int p = atomicAdd(&dcnt_s,1); dlist[p] = (b<<16)|(r<<12)|s; }
    }
    // score GEMM: 2b x 4r tile/warp (32 warps), lane splits K; j-paired fma.f32x2
    {
      ull acc2[8];
      #pragma unroll
      for (int z=0;z<8;z++) acc2[z]=0ull;
      #pragma unroll
      for (int hh=0; hh<2; hh++){
        int jb = sg_j0 + hh*4;
        ulonglong2 qa2[2], ra2[4];
        #pragma unroll
        for (int u=0;u<2;u++) qa2[u] = *(const ulonglong2*)&qks[(sg_bq0+u)*256 + jb];
        #pragma unroll
        for (int u=0;u<4;u++) ra2[u] = *(const ulonglong2*)&rowsf[(sg_r0+u)*256 + jb];
        #pragma unroll
        for (int bi=0;bi<2;bi++)
          #pragma unroll
          for (int ri=0;ri<4;ri++){
            fma2(acc2[bi*4+ri], qa2[bi].x, ra2[ri].x);
            fma2(acc2[bi*4+ri], qa2[bi].y, ra2[ri].y);
          }
      }
      float acc[8];
      #pragma unroll
      for (int z=0;z<8;z++) acc[z] = upk_sum(acc2[z]);
      {
        bool hi = (lane & 16);
        #pragma unroll
        for (int z=0;z<4;z++){
          float send = hi ? acc[z] : acc[z+4];
          float r = __shfl_xor_sync(0xffffffffu, send, 16);
          acc[z] = (hi ? acc[z+4] : acc[z]) + r;
        }
      }
      {
        bool hi = (lane & 8);
        #pragma unroll
        for (int z=0;z<2;z++){
          float send = hi ? acc[z] : acc[z+2];
          float r = __shfl_xor_sync(0xffffffffu, send, 8);
          acc[z] = (hi ? acc[z+2] : acc[z]) + r;
        }
      }
      {
        bool hi = (lane & 4);
        float send = hi ? acc[0] : acc[1];
        float r = __shfl_xor_sync(0xffffffffu, send, 4);
        acc[0] = (hi ? acc[1] : acc[0]) + r;
      }
      acc[0] += __shfl_xor_sync(0xffffffffu, acc[0], 2);
      acc[0] += __shfl_xor_sync(0xffffffffu, acc[0], 1);
      if ((lane & 3) == 0){
        int z = (lane>>2) & 7;
        sc[sg_bq0 + (z>>2)][sg_r0 + (z&3)] = acc[0];
      }
    }
    __syncthreads();
    int dn = dcnt_s;
    // dirty score fixes (32 warps over entries)
    for (int e=wid; e<dn; e+=32){
      int pk = dlist[e]; int eb = pk>>16, er = (pk>>12)&15, es = pk&0xfff;
      const float* ov = g_ovl + ((size_t)eb*OV + es)*DD;
      float a2 = 0.f;
      #pragma unroll
      for (int k=0;k<8;k++) a2 = fmaf(__ldcg(&ov[lane+32*k]), qks[eb*256 + lane+32*k], a2);
      #pragma unroll
      for (int off=16; off; off>>=1) a2 += __shfl_xor_sync(0xffffffffu, a2, off);
      if (lane==0) sc[eb][er] = a2;
    }
    __syncthreads();
    // exp + psum (warps 0-7) || candidate bitonic top-8 (warps 16-23) — concurrent
    if (tid < 256){
      int b = tid>>4, r = tid&15;
      float e = expf(sc[b][r]);
      float eo = __shfl_down_sync(0xffffffffu, e, 1);
      if ((r & 1) == 0) esm2[(r>>1)*16 + b] = pk2(e, eo);
      float ps = e;
      #pragma unroll
      for (int off=8; off; off>>=1) ps += __shfl_xor_sync(0xffffffffu, ps, off);
      if (r==0) __stcg(&g_psum[b*NB + blk], ps);
    } else if (wid >= 16 && wid < 24 && t < SS-1){
      int w2 = wid - 16;
      int hw = lane>>4, l4 = lane&15;
      int b = w2*2 + hw;
      float v = sc[b][l4];
      unsigned u = __float_as_uint(v);
      u = (u & 0x80000000u) ? ~u : (u | 0x80000000u);
      ull key = ((ull)u << 32) | (unsigned)(MM - (m0 + l4));
      #pragma unroll
      for (int k2=2; k2<=16; k2<<=1){
        #pragma unroll
        for (int j=k2>>1; j>0; j>>=1){
          ull o = __shfl_xor_sync(0xffffffffu, key, j);
          bool keep_max = ((l4 & k2)==0) == ((l4 & j)==0);
          key = keep_max ? (key > o ? key : o) : (key < o ? key : o);
        }
      }
      if (l4 < 8) __stcg(&g_ck[(size_t)(blk*BB+b)*TK + l4], key);
    }
    __syncthreads();
    // base partials: 4 threads per d; r-paired fma.f32x2
    {
      int d = tid>>2, q = tid&3;
      ull accp[4];
      #pragma unroll
      for (int z=0;z<4;z++) accp[z]=0ull;
      #pragma unroll
      for (int rp=0; rp<8; rp++){
        ull rrp = pk2(rowsf[(2*rp)*256 + d], rowsf[(2*rp+1)*256 + d]);
        const ulonglong2* ee2 = (const ulonglong2*)(esm2 + rp*16 + q*4);
        ulonglong2 eA = ee2[0], eB = ee2[1];
        fma2(accp[0], eA.x, rrp); fma2(accp[1], eA.y, rrp);
        fma2(accp[2], eB.x, rrp); fma2(accp[3], eB.y, rrp);
      }
      *(float4*)&sbuf[d*16 + q*4] =
        make_float4(upk_sum(accp[0]), upk_sum(accp[1]), upk_sum(accp[2]), upk_sum(accp[3]));
    }
    __syncthreads();
    // dirty partial corrections: 2 warps per batch (k-halves)
    {
      int cb = wid&15, khalf = wid>>4;
      float corr[4] = {0.f,0.f,0.f,0.f};
      bool any = false;
      for (int e=0;e<dn;e++){
        int pk = dlist[e];
        if ((pk>>16) == cb){
          int er = (pk>>12)&15, es = pk&0xfff;
          float ev = upk_sel(esm2[(er>>1)*16 + cb], er&1);
          const float* ov = g_ovl + ((size_t)cb*OV + es)*DD;
          any = true;
          #pragma unroll
          for (int kk=0;kk<4;kk++){
            int d = lane + 32*(khalf*4+kk);
            corr[kk] = fmaf(ev, __ldcg(&ov[d]) - rowsf[er*256 + d], corr[kk]);
          }
        }
      }
      if (any){
        #pragma unroll
        for (int kk=0;kk<4;kk++){ int d = lane + 32*(khalf*4+kk); sbuf[d*16 + cb] += corr[kk]; }
      }
    }
    __syncthreads();
    // store partials [k][d][b]
    {
      int d = tid>>2, q = tid&3;
      float4* gp4 = (float4*)g_part;
      __stcg(&gp4[((size_t)blk*256 + d)*4 + q], *(const float4*)&sbuf[d*16 + q*4]);
    }
    gbar(++bid);

    // ================= Phase C1 =================
    // h reduce for this block's d-chunk
    {
      const float4* gp4 = (const float4*)g_part;
      int q = tid&7, kg = tid>>3;   // kg 0..127
      float4 a4 = __ldcg(&gp4[((size_t)kg*256 + dd0 + (q>>2))*4 + (q&3)]);
      #pragma unroll
      for (int off=8; off<=16; off<<=1){
        a4.x += __shfl_xor_sync(0xffffffffu, a4.x, off);
        a4.y += __shfl_xor_sync(0xffffffffu, a4.y, off);
        a4.z += __shfl_xor_sync(0xffffffffu, a4.z, off);
        a4.w += __shfl_xor_sync(0xffffffffu, a4.w, off);
      }
      if (lane < 8) hred4[wid*8 + lane] = a4;
      __syncthreads();
      if (wid == 0){
        float4 a = hred4[lane];
        #pragma unroll
        for (int z=1;z<8;z++){
          float4 v = hred4[lane + 32*z];
          a.x+=v.x; a.y+=v.y; a.z+=v.z; a.w+=v.w;
        }
        #pragma unroll
        for (int off=8; off<=16; off<<=1){
          a.x += __shfl_xor_sync(0xffffffffu, a.x, off);
          a.y += __shfl_xor_sync(0xffffffffu, a.y, off);
          a.z += __shfl_xor_sync(0xffffffffu, a.z, off);
          a.w += __shfl_xor_sync(0xffffffffu, a.w, off);
        }
        if (lane < 8) __stcg(&((float4*)g_h)[dd0*4 + lane], a);
      }
    }
    // local 1/Z for all 16 batches (warps 0-15)
    if (wid < 16){
      const float4* ps4 = (const float4*)&g_psum[wid*NB];
      float4 p4 = __ldcg(&ps4[lane]);
      float zp = (p4.x+p4.y)+(p4.z+p4.w);
      #pragma unroll
      for (int off=16; off; off>>=1) zp += __shfl_xor_sync(0xffffffffu, zp, off);
      if (lane==0) zin_s[wid] = 1.0f/zp;
    }
    if (t+1 < SS){
      const float4* q4 = (const float4*)(g_qk + (size_t)(t+1)*BB*DD);
      float4* qd = (float4*)qks;
      for (int i=tid;i<1024;i+=NT) qd[i] = __ldcg(&q4[i]);
    }
    if (blk < BB && t < SS-1){
      int b2 = blk;
      // stage 1: warps 0-15 x 64 candidates -> per-warp top-8 (warp-local)
      if (wid < 16){
        ull k0, k1;
        {
          int c0 = wid*64 + lane;
          int c1 = wid*64 + 32 + lane;
          k0 = __ldcg(&g_ck[(size_t)((c0>>3)*BB + b2)*TK + (c0&7)]);
          k1 = __ldcg(&g_ck[(size_t)((c1>>3)*BB + b2)*TK + (c1&7)]);
        }
        #pragma unroll
        for (int round=0; round<TK; round++){
          ull k = k0 > k1 ? k0 : k1;
          #pragma unroll
          for (int off=16; off; off>>=1){
            ull o = __shfl_xor_sync(0xffffffffu, k, off);
            if (o > k) k = o;
          }
          if (lane == round) wtop[wid*8 + round] = k;
          if (k0 == k) k0 = 0ull;
          if (k1 == k) k1 = 0ull;
        }
      }
      __syncthreads();
      // stage 2: warp 0 merges 128 keys (4/lane)
      if (wid == 0){
        ull kl[4];
        kl[0] = wtop[lane]; kl[1] = wtop[lane+32];
        kl[2] = wtop[lane+64]; kl[3] = wtop[lane+96];
        int myrow = 0;
        #pragma unroll
        for (int round=0; round<TK; round++){
          ull k = kl[0];
          if (kl[1] > k) k = kl[1];
          if (kl[2] > k) k = kl[2];
          if (kl[3] > k) k = kl[3];
          #pragma unroll
          for (int off=16; off; off>>=1){
            ull o = __shfl_xor_sync(0xffffffffu, k, off);
            if (o > k) k = o;
          }
          if (lane == round) myrow = MM - (int)(unsigned)(k & 0xFFFFFFFFu);
          #pragma unroll
          for (int z=0;z<4;z++) if (kl[z]==k) kl[z] = 0ull;
        }
        bool valid = lane < TK;
        int row = valid ? myrow : 0;
        int s = valid ? __ldcg(&g_slot[b2*MM + row]) : 0;
        unsigned nm = __ballot_sync(0xffffffffu, valid && s < 0);
        int cnt0 = 0;
        if (lane==0) cnt0 = __ldcg(&g_ovcnt[b2]);
        cnt0 = __shfl_sync(0xffffffffu, cnt0, 0);
        if (valid){
          int prev = s, slot = s;
          if (s < 0){
            slot = cnt0 + __popc(nm & ((1u<<lane)-1));
            __stcg(&g_slot[b2*MM + row], slot);
          }
          __stcg(&g_tk[b2*24 + lane*3 + 0], row);
          __stcg(&g_tk[b2*24 + lane*3 + 1], prev);
          __stcg(&g_tk[b2*24 + lane*3 + 2], slot);
        }
        if (lane==0) __stcg(&g_ovcnt[b2], cnt0 + __popc(nm));
      }
    }
    gbar(++bid);

    // ================= Phase C2 =================
    {
      const float4* h4g = (const float4*)g_h;
      float4* s4 = (float4*)sbuf;
      for (int i=tid;i<1024;i+=NT) s4[i] = __ldcg(&h4g[i]);
      if (t < SS-1){
        for (int i=tid;i<BB*TK*3;i+=NT) tk_s[i] = __ldcg(&g_tk[i]);
      }
      __syncthreads();
      // GEMV over all 1024 threads (j-paired f32x2): b = tid&15, jseg = tid>>4 (4 j each)
      {
        int b = tid&15, jseg = tid>>4;
        ull a0p=0ull, a1p=0ull, a2p=0ull, a3p=0ull;
        #pragma unroll
        for (int jj=0;jj<2;jj++){
          int j = jseg*4 + jj*2;
          ull hvp = pk2(sbuf[j*16 + b], sbuf[j*16 + 16 + b]);
          fma2(a0p, *(const ull*)&wrow[j],       hvp);
          fma2(a1p, *(const ull*)&wrow[256 + j], hvp);
          fma2(a2p, *(const ull*)&wrow[512 + j], hvp);
          fma2(a3p, *(const ull*)&wrow[768 + j], hvp);
        }
        float a0 = upk_sum(a0p), a1 = upk_sum(a1p);
        float a2 = upk_sum(a2p), a3 = upk_sum(a3p);
        a0 += __shfl_xor_sync(0xffffffffu, a0, 16);
        a1 += __shfl_xor_sync(0xffffffffu, a1, 16);
        a2 += __shfl_xor_sync(0xffffffffu, a2, 16);
        a3 += __shfl_xor_sync(0xffffffffu, a3, 16);
        if ((tid&16)==0){
          cacc[b][0][wid]=a0; cacc[b][1][wid]=a1; cacc[b][2][wid]=a2; cacc[b][3][wid]=a3;
        }
      }
      __syncthreads();
      if (tid < 64){
        int b = tid&15, o = tid>>4;
        float s = 0.f;
        #pragma unroll
        for (int w=0;w<32;w++) s += cacc[b][o][w];
        float zi = zin_s[b];
        if (o < 2){
          out[((size_t)b*SS+t)*DD + dd0 + o] = s*zi + sbv[o];
        } else {
          int di = o-2;
          float gg = s*zi + scv[di] + __ldg(&g_gx[((size_t)t*BB+b)*DD + dd0 + di]);
          sgate[b][di] = 1.0f/(1.0f+expf(-gg));
        }
      }
      __syncthreads();
      if (t < SS-1 && tid < 256){
        int ent = tid>>1, di = tid&1;
        int b = ent>>3, i = ent&7;
        int row  = tk_s[(b*TK+i)*3 + 0];
        int prev = tk_s[(b*TK+i)*3 + 1];
        int slot = tk_s[(b*TK+i)*3 + 2];
        int d = dd0 + di;
        float old = (prev < 0) ? __ldg(&base[(size_t)row*DD + d])
                               : __ldcg(&g_ovl[((size_t)b*OV + prev)*DD + d]);
        float g = sgate[b][di];
        float xd = __ldg(&x[((size_t)b*SS+t)*DD + d]);
        __stcg(&g_ovl[((size_t)b*OV + slot)*DD + d], old + g*(xd - old));
      }
    }
    gbar(++bid);
  }
}

// =================== launch: single kernel ===================
extern "C" void kernel_launch(void* const* d_in, const int* in_sizes, int n_in,
                              void* d_out, int out_size){
  const float* x      = (const float*)d_in[0];
  const float* memory = (const float*)d_in[1];
  const float* Wq     = (const float*)d_in[2];
  const float* bq     = (const float*)d_in[3];
  const float* Wk     = (const float*)d_in[4];
  // bk contributes only a softmax-invariant constant -> dropped
  const float* Wv     = (const float*)d_in[6];
  const float* bv     = (const float*)d_in[7];
  const float* Wu     = (const float*)d_in[8];
  const float* bu     = (const float*)d_in[9];
  float* out = (float*)d_out;

  static int attr_done = 0;
  if (!attr_done){
    cudaFuncSetAttribute(persist, cudaFuncAttributeMaxDynamicSharedMemorySize, 49152);
    attr_done = 1;
  }

  persist<<<NB, NT, 49152>>>(x, memory, Wq, bq, Wk, Wv, bv, Wu, bu, out);
}